// round 8
// baseline (speedup 1.0000x reference)
#include <cuda_runtime.h>

#define T_LEVELS    21
#define IN_DIM      4096
#define OUT_DIM     32
#define BLK_BITS    13         // levels 0..12, bits of prefix P
#define PPB         8          // prefixes per block (= warps per block)
#define N_PRE       (4 + OUT_DIM)

// Scratch for precomputed dot products (allowed: __device__ global, no alloc).
__device__ float g_pre[N_PRE];

// Tree 2x2 affine maps, kernel-invariant -> constant bank (immediate operands
// in unrolled code, zero registers / zero LDS).
__constant__ float c_tl[T_LEVELS * 4];
__constant__ float c_tr[T_LEVELS * 4];
__constant__ float c_tbl[T_LEVELS * 2];
__constant__ float c_tbr[T_LEVELS * 2];

#define TREE_M(k, b, i) ((b) ? c_tr[(k) * 4 + (i)] : c_tl[(k) * 4 + (i)])
#define TREE_B(k, b, i) ((b) ? c_tbr[(k) * 2 + (i)] : c_tbl[(k) * 2 + (i)])

// ---------------------------------------------------------------------------
// Kernel 1: 36 dot products of x (4096) with rows of in_left/in_right/out_layer0
// ---------------------------------------------------------------------------
__global__ void precompute_kernel(const float* __restrict__ x,
                                  const float* __restrict__ wl,
                                  const float* __restrict__ wr,
                                  const float* __restrict__ bl,
                                  const float* __restrict__ br,
                                  const float* __restrict__ w0,
                                  const float* __restrict__ ob)
{
    int r = blockIdx.x;            // 0..35
    const float* src;
    if (r < 2)       src = wl + r * IN_DIM;
    else if (r < 4)  src = wr + (r - 2) * IN_DIM;
    else             src = w0 + (r - 4) * IN_DIM;

    const float4* x4 = reinterpret_cast<const float4*>(x);
    const float4* s4 = reinterpret_cast<const float4*>(src);
    float s = 0.0f;
    #pragma unroll
    for (int i = threadIdx.x; i < IN_DIM / 4; i += 256) {
        float4 a = x4[i], b = s4[i];
        s = fmaf(a.x, b.x, s);
        s = fmaf(a.y, b.y, s);
        s = fmaf(a.z, b.z, s);
        s = fmaf(a.w, b.w, s);
    }

    __shared__ float red[8];
    #pragma unroll
    for (int o = 16; o > 0; o >>= 1) s += __shfl_down_sync(0xffffffffu, s, o);
    if ((threadIdx.x & 31) == 0) red[threadIdx.x >> 5] = s;
    __syncthreads();
    if (threadIdx.x == 0) {
        float tot = 0.0f;
        for (int w = 0; w < 8; w++) tot += red[w];
        float add;
        if (r < 2)      add = bl[r];
        else if (r < 4) add = br[r - 2];
        else            add = ob[r - 4];
        g_pre[r] = tot + add;
    }
}

// ---------------------------------------------------------------------------
// Kernel 2: hierarchical binary-tree expansion, 8 prefixes per block.
//   Phase 1 (parallel): warp w computes the 13-level checkpoint for prefix
//                       P = blockIdx*8 + w into s_A13[w]/s_v13[w].
//   Per-thread precompute: levels 13..17 (branch bits w, rr are it-invariant)
//       composed into one affine map:
//          v18    = R·v13 + r
//          A18[c] = A13[c] + pa_c·vax + qa_c·vay + pb_c·vbx + qb_c·vby + k_c
//   Phase 2 (it=0..7): 2×LDS.128 + ~28 FMA to level 18; suffix levels 18..20
//       use constant-bank tree maps (immediate operands) -> 8 STG.128 rows.
// Row index: p = P | (w<<13) | (rr<<16) | (b1<<18) | (b2<<19), leaf = bit 20.
// Store: 8 lanes (c4 = lane&7) cover one full 128B row line.
// ---------------------------------------------------------------------------
__global__ void __launch_bounds__(256, 3)
tree_kernel(const float* __restrict__ wout, // (21,32,2)
            float* __restrict__ out)
{
    __shared__ float s_wout[T_LEVELS * 64];  // [k][c][j]
    __shared__ float s_pre[N_PRE];
    __shared__ __align__(16) float s_A13[PPB][OUT_DIM];
    __shared__ __align__(16) float s_v13[PPB][4];

    for (int i = threadIdx.x; i < T_LEVELS * 64; i += blockDim.x)
        s_wout[i] = wout[i];
    for (int i = threadIdx.x; i < N_PRE; i += blockDim.x)
        s_pre[i] = g_pre[i];
    __syncthreads();

    const float2* s_wout2 = reinterpret_cast<const float2*>(s_wout);
    const unsigned w    = threadIdx.x >> 5;        // warp id: phase-1 owner AND level 13..15 bits
    const unsigned lane = threadIdx.x & 31u;
    const unsigned Pb   = blockIdx.x * PPB;

    // ---- phase 1 (parallel): warp w computes checkpoint for prefix Pb + w ----
    {
        const unsigned P = Pb + w;
        int c = lane;                               // lane = channel
        float A = s_pre[4 + c];
        float vax = s_pre[0], vay = s_pre[2];
        float vbx = s_pre[1], vby = s_pre[3];
        #pragma unroll 1
        for (int k = 0; k < BLK_BITS; k++) {
            unsigned b = (P >> k) & 1u;
            float2 wv = s_wout2[k * 32 + c];
            float vsx = b ? vbx : vax;
            float vsy = b ? vby : vay;
            A = fmaf(wv.x, vsx, fmaf(wv.y, vsy, A));
            float m00 = TREE_M(k, b, 0), m01 = TREE_M(k, b, 1);
            float m10 = TREE_M(k, b, 2), m11 = TREE_M(k, b, 3);
            float c0  = TREE_B(k, b, 0), c1  = TREE_B(k, b, 1);
            float nax = fmaf(m00, vax, fmaf(m01, vay, c0));
            float nay = fmaf(m10, vax, fmaf(m11, vay, c1));
            float nbx = fmaf(m00, vbx, fmaf(m01, vby, c0));
            float nby = fmaf(m10, vbx, fmaf(m11, vby, c1));
            vax = nax; vay = nay; vbx = nbx; vby = nby;
        }
        s_A13[w][c] = A;
        if (lane == 0) {
            float4 v4; v4.x = vax; v4.y = vay; v4.z = vbx; v4.w = vby;
            *reinterpret_cast<float4*>(&s_v13[w][0]) = v4;
        }
    }

    const unsigned c4 = lane & 7u;                 // channel group (4 channels)
    const unsigned rr = lane >> 3;                 // 2 bits: levels 16..17

    // ---- per-thread affine composition of levels 13..17 (it-invariant) ----
    float R00 = 1.f, R01 = 0.f, R10 = 0.f, R11 = 1.f, rc0 = 0.f, rc1 = 0.f;
    float pa0 = 0.f, pa1 = 0.f, pa2 = 0.f, pa3 = 0.f;
    float qa0 = 0.f, qa1 = 0.f, qa2 = 0.f, qa3 = 0.f;
    float pb0 = 0.f, pb1 = 0.f, pb2 = 0.f, pb3 = 0.f;
    float qb0 = 0.f, qb1 = 0.f, qb2 = 0.f, qb3 = 0.f;
    float kk0 = 0.f, kk1 = 0.f, kk2 = 0.f, kk3 = 0.f;
    #pragma unroll
    for (int j = 0; j < 5; j++) {
        const int k = BLK_BITS + j;                 // 13..17 (compile-time)
        unsigned b = (j < 3) ? ((w >> j) & 1u) : ((rr >> (j - 3)) & 1u);
        float sA = b ? 0.f : 1.f;
        float sB = b ? 1.f : 0.f;
        const float2* W = s_wout2 + k * 32 + c4 * 4;
        #pragma unroll
        for (int i = 0; i < 4; i++) {
            float2 w2 = W[i];
            float wRx = fmaf(w2.x, R00, w2.y * R10);
            float wRy = fmaf(w2.x, R01, w2.y * R11);
            float kc  = fmaf(w2.x, rc0, w2.y * rc1);
            float* PA = (i == 0) ? &pa0 : (i == 1) ? &pa1 : (i == 2) ? &pa2 : &pa3;
            float* QA = (i == 0) ? &qa0 : (i == 1) ? &qa1 : (i == 2) ? &qa2 : &qa3;
            float* PB = (i == 0) ? &pb0 : (i == 1) ? &pb1 : (i == 2) ? &pb2 : &pb3;
            float* QB = (i == 0) ? &qb0 : (i == 1) ? &qb1 : (i == 2) ? &qb2 : &qb3;
            float* KK = (i == 0) ? &kk0 : (i == 1) ? &kk1 : (i == 2) ? &kk2 : &kk3;
            *PA = fmaf(sA, wRx, *PA);
            *QA = fmaf(sA, wRy, *QA);
            *PB = fmaf(sB, wRx, *PB);
            *QB = fmaf(sB, wRy, *QB);
            *KK += kc;
        }
        float m00 = TREE_M(k, b, 0), m01 = TREE_M(k, b, 1);
        float m10 = TREE_M(k, b, 2), m11 = TREE_M(k, b, 3);
        float c0  = TREE_B(k, b, 0), c1  = TREE_B(k, b, 1);
        float n00 = fmaf(m00, R00, m01 * R10), n01 = fmaf(m00, R01, m01 * R11);
        float n10 = fmaf(m10, R00, m11 * R10), n11 = fmaf(m10, R01, m11 * R11);
        float nr0 = fmaf(m00, rc0, fmaf(m01, rc1, c0));
        float nr1 = fmaf(m10, rc0, fmaf(m11, rc1, c1));
        R00 = n00; R01 = n01; R10 = n10; R11 = n11; rc0 = nr0; rc1 = nr1;
    }

    // ---- hoist per-c4 output weights for levels 18..20 into registers ----
    const float2* W18 = s_wout2 + 18 * 32 + c4 * 4;
    const float2* W19 = s_wout2 + 19 * 32 + c4 * 4;
    const float2* W20 = s_wout2 + 20 * 32 + c4 * 4;
    float2 u18a = W18[0], u18b = W18[1], u18c = W18[2], u18d = W18[3];
    float2 u19a = W19[0], u19b = W19[1], u19c = W19[2], u19d = W19[3];
    float2 u20a = W20[0], u20b = W20[1], u20c = W20[2], u20d = W20[3];

    __syncthreads();

    // ---- phase 2: expand each of the 8 checkpoints ----
    #pragma unroll 1
    for (int it = 0; it < PPB; ++it) {
        const float4 af = *reinterpret_cast<const float4*>(&s_A13[it][c4 * 4]);
        const float4 vf = *reinterpret_cast<const float4*>(&s_v13[it][0]);
        const float v13ax = vf.x, v13ay = vf.y, v13bx = vf.z, v13by = vf.w;

        // jump to level 18 via the composed affine map
        float A0 = fmaf(pa0, v13ax, fmaf(qa0, v13ay, fmaf(pb0, v13bx, fmaf(qb0, v13by, af.x + kk0))));
        float A1 = fmaf(pa1, v13ax, fmaf(qa1, v13ay, fmaf(pb1, v13bx, fmaf(qb1, v13by, af.y + kk1))));
        float A2 = fmaf(pa2, v13ax, fmaf(qa2, v13ay, fmaf(pb2, v13bx, fmaf(qb2, v13by, af.z + kk2))));
        float A3 = fmaf(pa3, v13ax, fmaf(qa3, v13ay, fmaf(pb3, v13bx, fmaf(qb3, v13by, af.w + kk3))));
        float vax = fmaf(R00, v13ax, fmaf(R01, v13ay, rc0));
        float vay = fmaf(R10, v13ax, fmaf(R11, v13ay, rc1));
        float vbx = fmaf(R00, v13bx, fmaf(R01, v13by, rc0));
        float vby = fmaf(R10, v13bx, fmaf(R11, v13by, rc1));

        const unsigned p_base = (Pb + it) | (w << 13) | (rr << 16);

        // suffix enumeration: b1 = s19 (level 18), b2 = s20 (level 19).
        // u fully unrolled -> b1/b2 literal -> tree maps are constant-bank
        // immediate operands (no regs, no LDS).
        #pragma unroll
        for (unsigned u = 0; u < 4; ++u) {
            const unsigned b1 = u & 1u, b2 = (u >> 1) & 1u;

            float vs18x = b1 ? vbx : vax;
            float vs18y = b1 ? vby : vay;
            float m00 = TREE_M(18, b1, 0), m01 = TREE_M(18, b1, 1);
            float m10 = TREE_M(18, b1, 2), m11 = TREE_M(18, b1, 3);
            float c0  = TREE_B(18, b1, 0), c1  = TREE_B(18, b1, 1);
            float pax = fmaf(m00, vax, fmaf(m01, vay, c0));
            float pay = fmaf(m10, vax, fmaf(m11, vay, c1));
            float pbx = fmaf(m00, vbx, fmaf(m01, vby, c0));
            float pby = fmaf(m10, vbx, fmaf(m11, vby, c1));

            float vs19x = b2 ? pbx : pax;
            float vs19y = b2 ? pby : pay;
            m00 = TREE_M(19, b2, 0); m01 = TREE_M(19, b2, 1);
            m10 = TREE_M(19, b2, 2); m11 = TREE_M(19, b2, 3);
            c0  = TREE_B(19, b2, 0); c1  = TREE_B(19, b2, 1);
            float qax = fmaf(m00, pax, fmaf(m01, pay, c0));
            float qay = fmaf(m10, pax, fmaf(m11, pay, c1));
            float qbx = fmaf(m00, pbx, fmaf(m01, pby, c0));
            float qby = fmaf(m10, pbx, fmaf(m11, pby, c1));

            float P0 = fmaf(u19a.x, vs19x, fmaf(u19a.y, vs19y,
                       fmaf(u18a.x, vs18x, fmaf(u18a.y, vs18y, A0))));
            float P1 = fmaf(u19b.x, vs19x, fmaf(u19b.y, vs19y,
                       fmaf(u18b.x, vs18x, fmaf(u18b.y, vs18y, A1))));
            float P2 = fmaf(u19c.x, vs19x, fmaf(u19c.y, vs19y,
                       fmaf(u18c.x, vs18x, fmaf(u18c.y, vs18y, A2))));
            float P3 = fmaf(u19d.x, vs19x, fmaf(u19d.y, vs19y,
                       fmaf(u18d.x, vs18x, fmaf(u18d.y, vs18y, A3))));

            unsigned p = p_base | (b1 << 18) | (b2 << 19);
            float* o = out + (size_t)p * OUT_DIM + c4 * 4;

            float4 r0, r1;
            r0.x = fmaf(u20a.x, qax, fmaf(u20a.y, qay, P0));
            r0.y = fmaf(u20b.x, qax, fmaf(u20b.y, qay, P1));
            r0.z = fmaf(u20c.x, qax, fmaf(u20c.y, qay, P2));
            r0.w = fmaf(u20d.x, qax, fmaf(u20d.y, qay, P3));
            r1.x = fmaf(u20a.x, qbx, fmaf(u20a.y, qby, P0));
            r1.y = fmaf(u20b.x, qbx, fmaf(u20b.y, qby, P1));
            r1.z = fmaf(u20c.x, qbx, fmaf(u20c.y, qby, P2));
            r1.w = fmaf(u20d.x, qbx, fmaf(u20d.y, qby, P3));

            __stcs(reinterpret_cast<float4*>(o), r0);
            __stcs(reinterpret_cast<float4*>(o + ((size_t)1u << 20) * OUT_DIM), r1);
        }
    }
}

// ---------------------------------------------------------------------------
extern "C" void kernel_launch(void* const* d_in, const int* in_sizes, int n_in,
                              void* d_out, int out_size)
{
    const float* x    = (const float*)d_in[0];
    const float* wl   = (const float*)d_in[1];
    const float* wr   = (const float*)d_in[2];
    const float* bl   = (const float*)d_in[3];
    const float* br   = (const float*)d_in[4];
    const float* tl   = (const float*)d_in[5];
    const float* tr   = (const float*)d_in[6];
    const float* tbl  = (const float*)d_in[7];
    const float* tbr  = (const float*)d_in[8];
    const float* w0   = (const float*)d_in[9];
    const float* wout = (const float*)d_in[10];
    const float* ob   = (const float*)d_in[11];

    // Device->constant copies (graph-capturable async DtoD).
    cudaMemcpyToSymbolAsync(c_tl,  tl,  T_LEVELS * 4 * sizeof(float), 0, cudaMemcpyDeviceToDevice, 0);
    cudaMemcpyToSymbolAsync(c_tr,  tr,  T_LEVELS * 4 * sizeof(float), 0, cudaMemcpyDeviceToDevice, 0);
    cudaMemcpyToSymbolAsync(c_tbl, tbl, T_LEVELS * 2 * sizeof(float), 0, cudaMemcpyDeviceToDevice, 0);
    cudaMemcpyToSymbolAsync(c_tbr, tbr, T_LEVELS * 2 * sizeof(float), 0, cudaMemcpyDeviceToDevice, 0);

    precompute_kernel<<<N_PRE, 256>>>(x, wl, wr, bl, br, w0, ob);

    tree_kernel<<<(1 << BLK_BITS) / PPB, 256>>>(wout, (float*)d_out);
}

// round 9
// speedup vs baseline: 1.0078x; 1.0078x over previous
#include <cuda_runtime.h>

#define T_LEVELS    21
#define IN_DIM      4096
#define OUT_DIM     32
#define BLK_BITS    13         // levels 0..12, bits of prefix P
#define PPB         8          // prefixes per block (= warps per block)
#define N_PRE       (4 + OUT_DIM)

// Scratch for precomputed dot products (allowed: __device__ global, no alloc).
__device__ float g_pre[N_PRE];

// Tree 2x2 affine maps in constant memory — used ONLY with literal indices
// (suffix levels 18/19 in the fully unrolled u-loop), where they fold into
// FFMA immediate c[][] operands: zero registers, zero extra instructions.
__constant__ float c_tl[T_LEVELS * 4];
__constant__ float c_tr[T_LEVELS * 4];
__constant__ float c_tbl[T_LEVELS * 2];
__constant__ float c_tbr[T_LEVELS * 2];

#define CTREE_M(k, b, i) ((b) ? c_tr[(k) * 4 + (i)] : c_tl[(k) * 4 + (i)])
#define CTREE_B(k, b, i) ((b) ? c_tbr[(k) * 2 + (i)] : c_tbl[(k) * 2 + (i)])

// ---------------------------------------------------------------------------
// Kernel 1: 36 dot products of x (4096) with rows of in_left/in_right/out_layer0
// ---------------------------------------------------------------------------
__global__ void precompute_kernel(const float* __restrict__ x,
                                  const float* __restrict__ wl,
                                  const float* __restrict__ wr,
                                  const float* __restrict__ bl,
                                  const float* __restrict__ br,
                                  const float* __restrict__ w0,
                                  const float* __restrict__ ob)
{
    int r = blockIdx.x;            // 0..35
    const float* src;
    if (r < 2)       src = wl + r * IN_DIM;
    else if (r < 4)  src = wr + (r - 2) * IN_DIM;
    else             src = w0 + (r - 4) * IN_DIM;

    const float4* x4 = reinterpret_cast<const float4*>(x);
    const float4* s4 = reinterpret_cast<const float4*>(src);
    float s = 0.0f;
    #pragma unroll
    for (int i = threadIdx.x; i < IN_DIM / 4; i += 256) {
        float4 a = x4[i], b = s4[i];
        s = fmaf(a.x, b.x, s);
        s = fmaf(a.y, b.y, s);
        s = fmaf(a.z, b.z, s);
        s = fmaf(a.w, b.w, s);
    }

    __shared__ float red[8];
    #pragma unroll
    for (int o = 16; o > 0; o >>= 1) s += __shfl_down_sync(0xffffffffu, s, o);
    if ((threadIdx.x & 31) == 0) red[threadIdx.x >> 5] = s;
    __syncthreads();
    if (threadIdx.x == 0) {
        float tot = 0.0f;
        for (int w = 0; w < 8; w++) tot += red[w];
        float add;
        if (r < 2)      add = bl[r];
        else if (r < 4) add = br[r - 2];
        else            add = ob[r - 4];
        g_pre[r] = tot + add;
    }
}

// ---------------------------------------------------------------------------
// Kernel 2: hierarchical binary-tree expansion, 8 prefixes per block.
//   Phase 1 (parallel): warp w computes the 13-level checkpoint for prefix
//       P = blockIdx*8 + w into s_A13[w]/s_v13[w].   [tree maps from SMEM —
//       dynamic indices must not touch the constant bank]
//   Per-thread precompute: levels 13..17 (branch bits w, rr it-invariant)
//       composed into one affine map (SMEM tree reads):
//          v18    = R·v13 + r
//          A18[c] = A13[c] + pa_c·vax + qa_c·vay + pb_c·vbx + qb_c·vby + k_c
//   Phase 2 (it=0..7): 2×LDS.128 + ~28 FMA to level 18; suffix levels 18/19
//       tree maps come from CONSTANT bank with literal indices (immediate
//       FFMA operands, no regs), output weights 18..20 register-hoisted.
// Row index: p = P | (w<<13) | (rr<<16) | (b1<<18) | (b2<<19), leaf = bit 20.
// Store: 8 lanes (c4 = lane&7) cover one full 128B row line per STG.128 group.
// ---------------------------------------------------------------------------
__global__ void __launch_bounds__(256, 3)
tree_kernel(const float* __restrict__ tl,   // (21,2,2)
            const float* __restrict__ tr,   // (21,2,2)
            const float* __restrict__ tbl,  // (21,2)
            const float* __restrict__ tbr,  // (21,2)
            const float* __restrict__ wout, // (21,32,2)
            float* __restrict__ out)
{
    __shared__ float s_wout[T_LEVELS * 64];  // [k][c][j]
    __shared__ float s_tree[T_LEVELS * 12];  // [k][branch]{m00,m01,m10,m11,b0,b1}
    __shared__ float s_pre[N_PRE];
    __shared__ __align__(16) float s_A13[PPB][OUT_DIM];
    __shared__ __align__(16) float s_v13[PPB][4];

    for (int i = threadIdx.x; i < T_LEVELS * 64; i += blockDim.x)
        s_wout[i] = wout[i];
    for (int i = threadIdx.x; i < T_LEVELS * 12; i += blockDim.x) {
        int k = i / 12, rem = i % 12, b = rem / 6, e = rem % 6;
        const float* M = b ? tr  : tl;
        const float* B = b ? tbr : tbl;
        s_tree[i] = (e < 4) ? M[k * 4 + e] : B[k * 2 + (e - 4)];
    }
    for (int i = threadIdx.x; i < N_PRE; i += blockDim.x)
        s_pre[i] = g_pre[i];
    __syncthreads();

    const float2* s_wout2 = reinterpret_cast<const float2*>(s_wout);
    const unsigned w    = threadIdx.x >> 5;        // warp id: phase-1 owner AND level 13..15 bits
    const unsigned lane = threadIdx.x & 31u;
    const unsigned Pb   = blockIdx.x * PPB;

    // ---- phase 1 (parallel): warp w computes checkpoint for prefix Pb + w ----
    {
        const unsigned P = Pb + w;
        int c = lane;                               // lane = channel
        float A = s_pre[4 + c];
        float vax = s_pre[0], vay = s_pre[2];
        float vbx = s_pre[1], vby = s_pre[3];
        #pragma unroll 1
        for (int k = 0; k < BLK_BITS; k++) {
            unsigned b = (P >> k) & 1u;
            float2 wv = s_wout2[k * 32 + c];
            float vsx = b ? vbx : vax;
            float vsy = b ? vby : vay;
            A = fmaf(wv.x, vsx, fmaf(wv.y, vsy, A));
            const float* M = s_tree + k * 12 + b * 6;
            float m00 = M[0], m01 = M[1], m10 = M[2], m11 = M[3], c0 = M[4], c1 = M[5];
            float nax = fmaf(m00, vax, fmaf(m01, vay, c0));
            float nay = fmaf(m10, vax, fmaf(m11, vay, c1));
            float nbx = fmaf(m00, vbx, fmaf(m01, vby, c0));
            float nby = fmaf(m10, vbx, fmaf(m11, vby, c1));
            vax = nax; vay = nay; vbx = nbx; vby = nby;
        }
        s_A13[w][c] = A;
        if (lane == 0) {
            float4 v4; v4.x = vax; v4.y = vay; v4.z = vbx; v4.w = vby;
            *reinterpret_cast<float4*>(&s_v13[w][0]) = v4;
        }
    }

    const unsigned c4 = lane & 7u;                 // channel group (4 channels)
    const unsigned rr = lane >> 3;                 // 2 bits: levels 16..17

    // ---- per-thread affine composition of levels 13..17 (it-invariant) ----
    float R00 = 1.f, R01 = 0.f, R10 = 0.f, R11 = 1.f, rc0 = 0.f, rc1 = 0.f;
    float pa0 = 0.f, pa1 = 0.f, pa2 = 0.f, pa3 = 0.f;
    float qa0 = 0.f, qa1 = 0.f, qa2 = 0.f, qa3 = 0.f;
    float pb0 = 0.f, pb1 = 0.f, pb2 = 0.f, pb3 = 0.f;
    float qb0 = 0.f, qb1 = 0.f, qb2 = 0.f, qb3 = 0.f;
    float kk0 = 0.f, kk1 = 0.f, kk2 = 0.f, kk3 = 0.f;
    #pragma unroll
    for (int j = 0; j < 5; j++) {
        const int k = BLK_BITS + j;                 // 13..17
        unsigned b = (j < 3) ? ((w >> j) & 1u) : ((rr >> (j - 3)) & 1u);
        float sA = b ? 0.f : 1.f;
        float sB = b ? 1.f : 0.f;
        const float2* W = s_wout2 + k * 32 + c4 * 4;
        #pragma unroll
        for (int i = 0; i < 4; i++) {
            float2 w2 = W[i];
            float wRx = fmaf(w2.x, R00, w2.y * R10);
            float wRy = fmaf(w2.x, R01, w2.y * R11);
            float kc  = fmaf(w2.x, rc0, w2.y * rc1);
            float* PA = (i == 0) ? &pa0 : (i == 1) ? &pa1 : (i == 2) ? &pa2 : &pa3;
            float* QA = (i == 0) ? &qa0 : (i == 1) ? &qa1 : (i == 2) ? &qa2 : &qa3;
            float* PB = (i == 0) ? &pb0 : (i == 1) ? &pb1 : (i == 2) ? &pb2 : &pb3;
            float* QB = (i == 0) ? &qb0 : (i == 1) ? &qb1 : (i == 2) ? &qb2 : &qb3;
            float* KK = (i == 0) ? &kk0 : (i == 1) ? &kk1 : (i == 2) ? &kk2 : &kk3;
            *PA = fmaf(sA, wRx, *PA);
            *QA = fmaf(sA, wRy, *QA);
            *PB = fmaf(sB, wRx, *PB);
            *QB = fmaf(sB, wRy, *QB);
            *KK += kc;
        }
        const float* M = s_tree + k * 12 + b * 6;   // SMEM (dynamic b)
        float m00 = M[0], m01 = M[1], m10 = M[2], m11 = M[3], c0 = M[4], c1 = M[5];
        float n00 = fmaf(m00, R00, m01 * R10), n01 = fmaf(m00, R01, m01 * R11);
        float n10 = fmaf(m10, R00, m11 * R10), n11 = fmaf(m10, R01, m11 * R11);
        float nr0 = fmaf(m00, rc0, fmaf(m01, rc1, c0));
        float nr1 = fmaf(m10, rc0, fmaf(m11, rc1, c1));
        R00 = n00; R01 = n01; R10 = n10; R11 = n11; rc0 = nr0; rc1 = nr1;
    }

    // ---- hoist per-c4 output weights for levels 18..20 into registers ----
    const float2* W18 = s_wout2 + 18 * 32 + c4 * 4;
    const float2* W19 = s_wout2 + 19 * 32 + c4 * 4;
    const float2* W20 = s_wout2 + 20 * 32 + c4 * 4;
    float2 u18a = W18[0], u18b = W18[1], u18c = W18[2], u18d = W18[3];
    float2 u19a = W19[0], u19b = W19[1], u19c = W19[2], u19d = W19[3];
    float2 u20a = W20[0], u20b = W20[1], u20c = W20[2], u20d = W20[3];

    __syncthreads();

    // ---- phase 2: expand each of the 8 checkpoints ----
    #pragma unroll 1
    for (int it = 0; it < PPB; ++it) {
        const float4 af = *reinterpret_cast<const float4*>(&s_A13[it][c4 * 4]);
        const float4 vf = *reinterpret_cast<const float4*>(&s_v13[it][0]);
        const float v13ax = vf.x, v13ay = vf.y, v13bx = vf.z, v13by = vf.w;

        // jump to level 18 via the composed affine map
        float A0 = fmaf(pa0, v13ax, fmaf(qa0, v13ay, fmaf(pb0, v13bx, fmaf(qb0, v13by, af.x + kk0))));
        float A1 = fmaf(pa1, v13ax, fmaf(qa1, v13ay, fmaf(pb1, v13bx, fmaf(qb1, v13by, af.y + kk1))));
        float A2 = fmaf(pa2, v13ax, fmaf(qa2, v13ay, fmaf(pb2, v13bx, fmaf(qb2, v13by, af.z + kk2))));
        float A3 = fmaf(pa3, v13ax, fmaf(qa3, v13ay, fmaf(pb3, v13bx, fmaf(qb3, v13by, af.w + kk3))));
        float vax = fmaf(R00, v13ax, fmaf(R01, v13ay, rc0));
        float vay = fmaf(R10, v13ax, fmaf(R11, v13ay, rc1));
        float vbx = fmaf(R00, v13bx, fmaf(R01, v13by, rc0));
        float vby = fmaf(R10, v13bx, fmaf(R11, v13by, rc1));

        const unsigned p_base = (Pb + it) | (w << 13) | (rr << 16);

        // suffix enumeration: b1 = s19 (level 18), b2 = s20 (level 19).
        // Fully unrolled -> b1/b2 literal -> constant-bank tree maps fold into
        // FFMA immediate operands (no registers, no LDS, no LDC).
        #pragma unroll
        for (unsigned u = 0; u < 4; ++u) {
            const unsigned b1 = u & 1u, b2 = (u >> 1) & 1u;

            float vs18x = b1 ? vbx : vax;
            float vs18y = b1 ? vby : vay;
            float m00 = CTREE_M(18, b1, 0), m01 = CTREE_M(18, b1, 1);
            float m10 = CTREE_M(18, b1, 2), m11 = CTREE_M(18, b1, 3);
            float c0  = CTREE_B(18, b1, 0), c1  = CTREE_B(18, b1, 1);
            float pax = fmaf(m00, vax, fmaf(m01, vay, c0));
            float pay = fmaf(m10, vax, fmaf(m11, vay, c1));
            float pbx = fmaf(m00, vbx, fmaf(m01, vby, c0));
            float pby = fmaf(m10, vbx, fmaf(m11, vby, c1));

            float vs19x = b2 ? pbx : pax;
            float vs19y = b2 ? pby : pay;
            m00 = CTREE_M(19, b2, 0); m01 = CTREE_M(19, b2, 1);
            m10 = CTREE_M(19, b2, 2); m11 = CTREE_M(19, b2, 3);
            c0  = CTREE_B(19, b2, 0); c1  = CTREE_B(19, b2, 1);
            float qax = fmaf(m00, pax, fmaf(m01, pay, c0));
            float qay = fmaf(m10, pax, fmaf(m11, pay, c1));
            float qbx = fmaf(m00, pbx, fmaf(m01, pby, c0));
            float qby = fmaf(m10, pbx, fmaf(m11, pby, c1));

            float P0 = fmaf(u19a.x, vs19x, fmaf(u19a.y, vs19y,
                       fmaf(u18a.x, vs18x, fmaf(u18a.y, vs18y, A0))));
            float P1 = fmaf(u19b.x, vs19x, fmaf(u19b.y, vs19y,
                       fmaf(u18b.x, vs18x, fmaf(u18b.y, vs18y, A1))));
            float P2 = fmaf(u19c.x, vs19x, fmaf(u19c.y, vs19y,
                       fmaf(u18c.x, vs18x, fmaf(u18c.y, vs18y, A2))));
            float P3 = fmaf(u19d.x, vs19x, fmaf(u19d.y, vs19y,
                       fmaf(u18d.x, vs18x, fmaf(u18d.y, vs18y, A3))));

            unsigned p = p_base | (b1 << 18) | (b2 << 19);
            float* o = out + (size_t)p * OUT_DIM + c4 * 4;

            float4 r0, r1;
            r0.x = fmaf(u20a.x, qax, fmaf(u20a.y, qay, P0));
            r0.y = fmaf(u20b.x, qax, fmaf(u20b.y, qay, P1));
            r0.z = fmaf(u20c.x, qax, fmaf(u20c.y, qay, P2));
            r0.w = fmaf(u20d.x, qax, fmaf(u20d.y, qay, P3));
            r1.x = fmaf(u20a.x, qbx, fmaf(u20a.y, qby, P0));
            r1.y = fmaf(u20b.x, qbx, fmaf(u20b.y, qby, P1));
            r1.z = fmaf(u20c.x, qbx, fmaf(u20c.y, qby, P2));
            r1.w = fmaf(u20d.x, qbx, fmaf(u20d.y, qby, P3));

            __stcs(reinterpret_cast<float4*>(o), r0);
            __stcs(reinterpret_cast<float4*>(o + ((size_t)1u << 20) * OUT_DIM), r1);
        }
    }
}

// ---------------------------------------------------------------------------
extern "C" void kernel_launch(void* const* d_in, const int* in_sizes, int n_in,
                              void* d_out, int out_size)
{
    const float* x    = (const float*)d_in[0];
    const float* wl   = (const float*)d_in[1];
    const float* wr   = (const float*)d_in[2];
    const float* bl   = (const float*)d_in[3];
    const float* br   = (const float*)d_in[4];
    const float* tl   = (const float*)d_in[5];
    const float* tr   = (const float*)d_in[6];
    const float* tbl  = (const float*)d_in[7];
    const float* tbr  = (const float*)d_in[8];
    const float* w0   = (const float*)d_in[9];
    const float* wout = (const float*)d_in[10];
    const float* ob   = (const float*)d_in[11];

    precompute_kernel<<<N_PRE, 256>>>(x, wl, wr, bl, br, w0, ob);

    // Device->constant copies (graph-capturable async DtoD, 336 B total).
    cudaMemcpyToSymbolAsync(c_tl,  tl,  T_LEVELS * 4 * sizeof(float), 0, cudaMemcpyDeviceToDevice, 0);
    cudaMemcpyToSymbolAsync(c_tr,  tr,  T_LEVELS * 4 * sizeof(float), 0, cudaMemcpyDeviceToDevice, 0);
    cudaMemcpyToSymbolAsync(c_tbl, tbl, T_LEVELS * 2 * sizeof(float), 0, cudaMemcpyDeviceToDevice, 0);
    cudaMemcpyToSymbolAsync(c_tbr, tbr, T_LEVELS * 2 * sizeof(float), 0, cudaMemcpyDeviceToDevice, 0);

    tree_kernel<<<(1 << BLK_BITS) / PPB, 256>>>(tl, tr, tbl, tbr, wout, (float*)d_out);
}

// round 10
// speedup vs baseline: 1.1597x; 1.1507x over previous
#include <cuda_runtime.h>

#define T_LEVELS    21
#define IN_DIM      4096
#define OUT_DIM     32
#define BLK_BITS    13         // levels 0..12, bits of prefix P
#define PPB         16         // prefixes per block (2 per warp, interleaved)
#define N_PRE       (4 + OUT_DIM)
#define N_PART      4          // precompute partial splits per row

// Scratch: partial dot products (allowed: __device__ global, no alloc).
__device__ float g_part[N_PRE * N_PART];

// ---------------------------------------------------------------------------
// Kernel 1: 36 dot products of x (4096) with rows of in_left/in_right/out_layer0,
// split 4-ways per row for latency (144 small blocks).
//   row r, part j: sum over elements [j*1024, (j+1)*1024); bias added at j==0.
// ---------------------------------------------------------------------------
__global__ void precompute_kernel(const float* __restrict__ x,
                                  const float* __restrict__ wl,
                                  const float* __restrict__ wr,
                                  const float* __restrict__ bl,
                                  const float* __restrict__ br,
                                  const float* __restrict__ w0,
                                  const float* __restrict__ ob)
{
    int r = blockIdx.x >> 2;       // 0..35
    int j = blockIdx.x & 3;        // part 0..3
    const float* src;
    if (r < 2)       src = wl + r * IN_DIM;
    else if (r < 4)  src = wr + (r - 2) * IN_DIM;
    else             src = w0 + (r - 4) * IN_DIM;

    const float4* x4 = reinterpret_cast<const float4*>(x) + j * 256;
    const float4* s4 = reinterpret_cast<const float4*>(src) + j * 256;
    // 256 threads, each handles exactly one float4
    float4 a = x4[threadIdx.x], b = s4[threadIdx.x];
    float s = fmaf(a.x, b.x, fmaf(a.y, b.y, fmaf(a.z, b.z, a.w * b.w)));

    __shared__ float red[8];
    #pragma unroll
    for (int o = 16; o > 0; o >>= 1) s += __shfl_down_sync(0xffffffffu, s, o);
    if ((threadIdx.x & 31) == 0) red[threadIdx.x >> 5] = s;
    __syncthreads();
    if (threadIdx.x == 0) {
        float tot = 0.0f;
        #pragma unroll
        for (int ww = 0; ww < 8; ww++) tot += red[ww];
        if (j == 0) {
            if (r < 2)      tot += bl[r];
            else if (r < 4) tot += br[r - 2];
            else            tot += ob[r - 4];
        }
        g_part[r * N_PART + j] = tot;
    }
}

// ---------------------------------------------------------------------------
// Kernel 2: hierarchical binary-tree expansion, 16 prefixes per block.
//   Phase 1 (parallel + ILP): warp w computes 13-level checkpoints for TWO
//       prefixes (Pb+2w, Pb+2w+1) with interleaved dependency chains, sharing
//       the per-level weight LDS. Stored to s_A13[2w],[2w+1].
//   Per-thread precompute: levels 13..17 (branch bits w, rr it-invariant)
//       composed into one affine map:
//          v18    = R·v13 + r
//          A18[c] = A13[c] + pa_c·vax + qa_c·vay + pb_c·vbx + qb_c·vby + k_c
//   Phase 2 (it=0..15): 2×LDS.128 + ~28 FMA to level 18, then the fully
//       register-hoisted suffix (levels 18..20) emits 8 rows via STG.128.
// Row index: p = (Pb+it) | (w<<13) | (rr<<16) | (b1<<18) | (b2<<19), leaf=bit20.
// Store: 8 lanes (c4 = lane&7) cover one full 128B row line.
// ---------------------------------------------------------------------------
__global__ void __launch_bounds__(256, 2)
tree_kernel(const float* __restrict__ tl,   // (21,2,2)
            const float* __restrict__ tr,   // (21,2,2)
            const float* __restrict__ tbl,  // (21,2)
            const float* __restrict__ tbr,  // (21,2)
            const float* __restrict__ wout, // (21,32,2)
            float* __restrict__ out)
{
    __shared__ float s_wout[T_LEVELS * 64];  // [k][c][j]
    __shared__ float s_tree[T_LEVELS * 12];  // [k][branch]{m00,m01,m10,m11,b0,b1}
    __shared__ float s_pre[N_PRE];
    __shared__ __align__(16) float s_A13[PPB][OUT_DIM];
    __shared__ __align__(16) float s_v13[PPB][4];

    for (int i = threadIdx.x; i < T_LEVELS * 64; i += blockDim.x)
        s_wout[i] = wout[i];
    for (int i = threadIdx.x; i < T_LEVELS * 12; i += blockDim.x) {
        int k = i / 12, rem = i % 12, b = rem / 6, e = rem % 6;
        const float* M = b ? tr  : tl;
        const float* B = b ? tbr : tbl;
        s_tree[i] = (e < 4) ? M[k * 4 + e] : B[k * 2 + (e - 4)];
    }
    for (int i = threadIdx.x; i < N_PRE; i += blockDim.x)
        s_pre[i] = g_part[i * N_PART + 0] + g_part[i * N_PART + 1]
                 + g_part[i * N_PART + 2] + g_part[i * N_PART + 3];
    __syncthreads();

    const float2* s_wout2 = reinterpret_cast<const float2*>(s_wout);
    const unsigned w    = threadIdx.x >> 5;        // warp id (3 bits: levels 13..15)
    const unsigned lane = threadIdx.x & 31u;
    const unsigned Pb   = blockIdx.x * PPB;

    // ---- phase 1: warp w computes checkpoints for prefixes Pb+2w, Pb+2w+1 ----
    {
        const unsigned Pe = Pb + 2 * w;             // even prefix
        const unsigned Po = Pe + 1;                 // odd prefix
        int c = lane;                               // lane = channel
        float Ae = s_pre[4 + c], Ao = Ae;
        float eax = s_pre[0], eay = s_pre[2], ebx = s_pre[1], eby = s_pre[3];
        float oax = eax, oay = eay, obx = ebx, oby = eby;
        #pragma unroll 1
        for (int k = 0; k < BLK_BITS; k++) {
            float2 wv = s_wout2[k * 32 + c];        // shared by both chains
            unsigned be = (Pe >> k) & 1u;
            unsigned bo = (Po >> k) & 1u;
            const float* Me = s_tree + k * 12 + be * 6;
            const float* Mo = s_tree + k * 12 + bo * 6;
            // chain E
            {
                float vsx = be ? ebx : eax;
                float vsy = be ? eby : eay;
                Ae = fmaf(wv.x, vsx, fmaf(wv.y, vsy, Ae));
                float m00 = Me[0], m01 = Me[1], m10 = Me[2], m11 = Me[3], c0 = Me[4], c1 = Me[5];
                float nax = fmaf(m00, eax, fmaf(m01, eay, c0));
                float nay = fmaf(m10, eax, fmaf(m11, eay, c1));
                float nbx = fmaf(m00, ebx, fmaf(m01, eby, c0));
                float nby = fmaf(m10, ebx, fmaf(m11, eby, c1));
                eax = nax; eay = nay; ebx = nbx; eby = nby;
            }
            // chain O (independent -> ILP hides latency)
            {
                float vsx = bo ? obx : oax;
                float vsy = bo ? oby : oay;
                Ao = fmaf(wv.x, vsx, fmaf(wv.y, vsy, Ao));
                float m00 = Mo[0], m01 = Mo[1], m10 = Mo[2], m11 = Mo[3], c0 = Mo[4], c1 = Mo[5];
                float nax = fmaf(m00, oax, fmaf(m01, oay, c0));
                float nay = fmaf(m10, oax, fmaf(m11, oay, c1));
                float nbx = fmaf(m00, obx, fmaf(m01, oby, c0));
                float nby = fmaf(m10, obx, fmaf(m11, oby, c1));
                oax = nax; oay = nay; obx = nbx; oby = nby;
            }
        }
        s_A13[2 * w][c] = Ae;
        s_A13[2 * w + 1][c] = Ao;
        if (lane == 0) {
            float4 v4; v4.x = eax; v4.y = eay; v4.z = ebx; v4.w = eby;
            *reinterpret_cast<float4*>(&s_v13[2 * w][0]) = v4;
            float4 u4; u4.x = oax; u4.y = oay; u4.z = obx; u4.w = oby;
            *reinterpret_cast<float4*>(&s_v13[2 * w + 1][0]) = u4;
        }
    }

    const unsigned c4 = lane & 7u;                 // channel group (4 channels)
    const unsigned rr = lane >> 3;                 // 2 bits: levels 16..17

    // ---- per-thread affine composition of levels 13..17 (it-invariant) ----
    float R00 = 1.f, R01 = 0.f, R10 = 0.f, R11 = 1.f, rc0 = 0.f, rc1 = 0.f;
    float pa0 = 0.f, pa1 = 0.f, pa2 = 0.f, pa3 = 0.f;
    float qa0 = 0.f, qa1 = 0.f, qa2 = 0.f, qa3 = 0.f;
    float pb0 = 0.f, pb1 = 0.f, pb2 = 0.f, pb3 = 0.f;
    float qb0 = 0.f, qb1 = 0.f, qb2 = 0.f, qb3 = 0.f;
    float kk0 = 0.f, kk1 = 0.f, kk2 = 0.f, kk3 = 0.f;
    #pragma unroll
    for (int j = 0; j < 5; j++) {
        const int k = BLK_BITS + j;                 // 13..17
        unsigned b = (j < 3) ? ((w >> j) & 1u) : ((rr >> (j - 3)) & 1u);
        float sA = b ? 0.f : 1.f;
        float sB = b ? 1.f : 0.f;
        const float2* W = s_wout2 + k * 32 + c4 * 4;
        #pragma unroll
        for (int i = 0; i < 4; i++) {
            float2 w2 = W[i];
            float wRx = fmaf(w2.x, R00, w2.y * R10);
            float wRy = fmaf(w2.x, R01, w2.y * R11);
            float kc  = fmaf(w2.x, rc0, w2.y * rc1);
            float* PA = (i == 0) ? &pa0 : (i == 1) ? &pa1 : (i == 2) ? &pa2 : &pa3;
            float* QA = (i == 0) ? &qa0 : (i == 1) ? &qa1 : (i == 2) ? &qa2 : &qa3;
            float* PB = (i == 0) ? &pb0 : (i == 1) ? &pb1 : (i == 2) ? &pb2 : &pb3;
            float* QB = (i == 0) ? &qb0 : (i == 1) ? &qb1 : (i == 2) ? &qb2 : &qb3;
            float* KK = (i == 0) ? &kk0 : (i == 1) ? &kk1 : (i == 2) ? &kk2 : &kk3;
            *PA = fmaf(sA, wRx, *PA);
            *QA = fmaf(sA, wRy, *QA);
            *PB = fmaf(sB, wRx, *PB);
            *QB = fmaf(sB, wRy, *QB);
            *KK += kc;
        }
        const float* M = s_tree + k * 12 + b * 6;
        float m00 = M[0], m01 = M[1], m10 = M[2], m11 = M[3], c0 = M[4], c1 = M[5];
        float n00 = fmaf(m00, R00, m01 * R10), n01 = fmaf(m00, R01, m01 * R11);
        float n10 = fmaf(m10, R00, m11 * R10), n11 = fmaf(m10, R01, m11 * R11);
        float nr0 = fmaf(m00, rc0, fmaf(m01, rc1, c0));
        float nr1 = fmaf(m10, rc0, fmaf(m11, rc1, c1));
        R00 = n00; R01 = n01; R10 = n10; R11 = n11; rc0 = nr0; rc1 = nr1;
    }

    // ---- hoist ALL suffix constants (levels 18..20) into registers ----
    const float2* W18 = s_wout2 + 18 * 32 + c4 * 4;
    const float2* W19 = s_wout2 + 19 * 32 + c4 * 4;
    const float2* W20 = s_wout2 + 20 * 32 + c4 * 4;
    float2 u18a = W18[0], u18b = W18[1], u18c = W18[2], u18d = W18[3];
    float2 u19a = W19[0], u19b = W19[1], u19c = W19[2], u19d = W19[3];
    float2 u20a = W20[0], u20b = W20[1], u20c = W20[2], u20d = W20[3];
    float M18[12], M19[12];
    #pragma unroll
    for (int i = 0; i < 12; i++) M18[i] = s_tree[18 * 12 + i];
    #pragma unroll
    for (int i = 0; i < 12; i++) M19[i] = s_tree[19 * 12 + i];

    __syncthreads();

    // ---- phase 2: expand each of the 16 checkpoints ----
    #pragma unroll 1
    for (int it = 0; it < PPB; ++it) {
        const float4 af = *reinterpret_cast<const float4*>(&s_A13[it][c4 * 4]);
        const float4 vf = *reinterpret_cast<const float4*>(&s_v13[it][0]);
        const float v13ax = vf.x, v13ay = vf.y, v13bx = vf.z, v13by = vf.w;

        // jump to level 18 via the composed affine map
        float A0 = fmaf(pa0, v13ax, fmaf(qa0, v13ay, fmaf(pb0, v13bx, fmaf(qb0, v13by, af.x + kk0))));
        float A1 = fmaf(pa1, v13ax, fmaf(qa1, v13ay, fmaf(pb1, v13bx, fmaf(qb1, v13by, af.y + kk1))));
        float A2 = fmaf(pa2, v13ax, fmaf(qa2, v13ay, fmaf(pb2, v13bx, fmaf(qb2, v13by, af.z + kk2))));
        float A3 = fmaf(pa3, v13ax, fmaf(qa3, v13ay, fmaf(pb3, v13bx, fmaf(qb3, v13by, af.w + kk3))));
        float vax = fmaf(R00, v13ax, fmaf(R01, v13ay, rc0));
        float vay = fmaf(R10, v13ax, fmaf(R11, v13ay, rc1));
        float vbx = fmaf(R00, v13bx, fmaf(R01, v13by, rc0));
        float vby = fmaf(R10, v13bx, fmaf(R11, v13by, rc1));

        const unsigned p_base = (Pb + it) | (w << 13) | (rr << 16);

        // suffix enumeration: b1 = s19 (level 18), b2 = s20 (level 19)
        #pragma unroll
        for (unsigned u = 0; u < 4; ++u) {
            const unsigned b1 = u & 1u, b2 = (u >> 1) & 1u;

            float vs18x = b1 ? vbx : vax;
            float vs18y = b1 ? vby : vay;
            float m00 = M18[b1 * 6 + 0], m01 = M18[b1 * 6 + 1];
            float m10 = M18[b1 * 6 + 2], m11 = M18[b1 * 6 + 3];
            float c0  = M18[b1 * 6 + 4], c1  = M18[b1 * 6 + 5];
            float pax = fmaf(m00, vax, fmaf(m01, vay, c0));
            float pay = fmaf(m10, vax, fmaf(m11, vay, c1));
            float pbx = fmaf(m00, vbx, fmaf(m01, vby, c0));
            float pby = fmaf(m10, vbx, fmaf(m11, vby, c1));

            float vs19x = b2 ? pbx : pax;
            float vs19y = b2 ? pby : pay;
            m00 = M19[b2 * 6 + 0]; m01 = M19[b2 * 6 + 1];
            m10 = M19[b2 * 6 + 2]; m11 = M19[b2 * 6 + 3];
            c0  = M19[b2 * 6 + 4]; c1  = M19[b2 * 6 + 5];
            float qax = fmaf(m00, pax, fmaf(m01, pay, c0));
            float qay = fmaf(m10, pax, fmaf(m11, pay, c1));
            float qbx = fmaf(m00, pbx, fmaf(m01, pby, c0));
            float qby = fmaf(m10, pbx, fmaf(m11, pby, c1));

            float P0 = fmaf(u19a.x, vs19x, fmaf(u19a.y, vs19y,
                       fmaf(u18a.x, vs18x, fmaf(u18a.y, vs18y, A0))));
            float P1 = fmaf(u19b.x, vs19x, fmaf(u19b.y, vs19y,
                       fmaf(u18b.x, vs18x, fmaf(u18b.y, vs18y, A1))));
            float P2 = fmaf(u19c.x, vs19x, fmaf(u19c.y, vs19y,
                       fmaf(u18c.x, vs18x, fmaf(u18c.y, vs18y, A2))));
            float P3 = fmaf(u19d.x, vs19x, fmaf(u19d.y, vs19y,
                       fmaf(u18d.x, vs18x, fmaf(u18d.y, vs18y, A3))));

            unsigned p = p_base | (b1 << 18) | (b2 << 19);
            float* o = out + (size_t)p * OUT_DIM + c4 * 4;

            float4 r0, r1;
            r0.x = fmaf(u20a.x, qax, fmaf(u20a.y, qay, P0));
            r0.y = fmaf(u20b.x, qax, fmaf(u20b.y, qay, P1));
            r0.z = fmaf(u20c.x, qax, fmaf(u20c.y, qay, P2));
            r0.w = fmaf(u20d.x, qax, fmaf(u20d.y, qay, P3));
            r1.x = fmaf(u20a.x, qbx, fmaf(u20a.y, qby, P0));
            r1.y = fmaf(u20b.x, qbx, fmaf(u20b.y, qby, P1));
            r1.z = fmaf(u20c.x, qbx, fmaf(u20c.y, qby, P2));
            r1.w = fmaf(u20d.x, qbx, fmaf(u20d.y, qby, P3));

            __stcs(reinterpret_cast<float4*>(o), r0);
            __stcs(reinterpret_cast<float4*>(o + ((size_t)1u << 20) * OUT_DIM), r1);
        }
    }
}

// ---------------------------------------------------------------------------
extern "C" void kernel_launch(void* const* d_in, const int* in_sizes, int n_in,
                              void* d_out, int out_size)
{
    const float* x    = (const float*)d_in[0];
    const float* wl   = (const float*)d_in[1];
    const float* wr   = (const float*)d_in[2];
    const float* bl   = (const float*)d_in[3];
    const float* br   = (const float*)d_in[4];
    const float* tl   = (const float*)d_in[5];
    const float* tr   = (const float*)d_in[6];
    const float* tbl  = (const float*)d_in[7];
    const float* tbr  = (const float*)d_in[8];
    const float* w0   = (const float*)d_in[9];
    const float* wout = (const float*)d_in[10];
    const float* ob   = (const float*)d_in[11];

    precompute_kernel<<<N_PRE * N_PART, 256>>>(x, wl, wr, bl, br, w0, ob);

    tree_kernel<<<(1 << BLK_BITS) / PPB, 256>>>(tl, tr, tbl, tbr, wout, (float*)d_out);
}

// round 11
// speedup vs baseline: 1.2159x; 1.0484x over previous
#include <cuda_runtime.h>

#define T_LEVELS    21
#define IN_DIM      4096
#define OUT_DIM     32
#define BLK_BITS    13         // levels 0..12, bits of prefix P
#define PPB         8          // prefixes per block (= warps per block)
#define N_PRE       (4 + OUT_DIM)
#define N_PART      4          // precompute partial splits per row

// Scratch: partial dot products (allowed: __device__ global, no alloc).
__device__ float g_part[N_PRE * N_PART];

// ---------------------------------------------------------------------------
// Kernel 1: 36 dot products of x (4096) with rows of in_left/in_right/out_layer0,
// split 4-ways per row for latency (144 small blocks run fully parallel).
//   row r, part j: sum over elements [j*1024, (j+1)*1024); bias added at j==0.
// ---------------------------------------------------------------------------
__global__ void precompute_kernel(const float* __restrict__ x,
                                  const float* __restrict__ wl,
                                  const float* __restrict__ wr,
                                  const float* __restrict__ bl,
                                  const float* __restrict__ br,
                                  const float* __restrict__ w0,
                                  const float* __restrict__ ob)
{
    int r = blockIdx.x >> 2;       // 0..35
    int j = blockIdx.x & 3;        // part 0..3
    const float* src;
    if (r < 2)       src = wl + r * IN_DIM;
    else if (r < 4)  src = wr + (r - 2) * IN_DIM;
    else             src = w0 + (r - 4) * IN_DIM;

    const float4* x4 = reinterpret_cast<const float4*>(x) + j * 256;
    const float4* s4 = reinterpret_cast<const float4*>(src) + j * 256;
    float4 a = x4[threadIdx.x], b = s4[threadIdx.x];
    float s = fmaf(a.x, b.x, fmaf(a.y, b.y, fmaf(a.z, b.z, a.w * b.w)));

    __shared__ float red[8];
    #pragma unroll
    for (int o = 16; o > 0; o >>= 1) s += __shfl_down_sync(0xffffffffu, s, o);
    if ((threadIdx.x & 31) == 0) red[threadIdx.x >> 5] = s;
    __syncthreads();
    if (threadIdx.x == 0) {
        float tot = 0.0f;
        #pragma unroll
        for (int ww = 0; ww < 8; ww++) tot += red[ww];
        if (j == 0) {
            if (r < 2)      tot += bl[r];
            else if (r < 4) tot += br[r - 2];
            else            tot += ob[r - 4];
        }
        g_part[r * N_PART + j] = tot;
    }
}

// ---------------------------------------------------------------------------
// Kernel 2 (R7 structure — the measured optimum): hierarchical binary-tree
// expansion, 8 prefixes per block.
//   Phase 1 (parallel): warp w computes the 13-level checkpoint for prefix
//       P = blockIdx*8 + w into s_A13[w]/s_v13[w].
//   Per-thread precompute: levels 13..17 (branch bits w, rr it-invariant)
//       composed into one affine map:
//          v18    = R·v13 + r
//          A18[c] = A13[c] + pa_c·vax + qa_c·vay + pb_c·vbx + qb_c·vby + k_c
//   Phase 2 (it=0..7): 2×LDS.128 + ~28 FMA to level 18, then the fully
//       register-hoisted suffix (levels 18..20) emits 8 rows via STG.128.
// Row index: p = (Pb+it) | (w<<13) | (rr<<16) | (b1<<18) | (b2<<19), leaf=bit20.
// Store: 8 lanes (c4 = lane&7) cover one full 128B row line.
// ---------------------------------------------------------------------------
__global__ void __launch_bounds__(256, 2)
tree_kernel(const float* __restrict__ tl,   // (21,2,2)
            const float* __restrict__ tr,   // (21,2,2)
            const float* __restrict__ tbl,  // (21,2)
            const float* __restrict__ tbr,  // (21,2)
            const float* __restrict__ wout, // (21,32,2)
            float* __restrict__ out)
{
    __shared__ float s_wout[T_LEVELS * 64];  // [k][c][j]
    __shared__ float s_tree[T_LEVELS * 12];  // [k][branch]{m00,m01,m10,m11,b0,b1}
    __shared__ float s_pre[N_PRE];
    __shared__ __align__(16) float s_A13[PPB][OUT_DIM];
    __shared__ __align__(16) float s_v13[PPB][4];

    for (int i = threadIdx.x; i < T_LEVELS * 64; i += blockDim.x)
        s_wout[i] = wout[i];
    for (int i = threadIdx.x; i < T_LEVELS * 12; i += blockDim.x) {
        int k = i / 12, rem = i % 12, b = rem / 6, e = rem % 6;
        const float* M = b ? tr  : tl;
        const float* B = b ? tbr : tbl;
        s_tree[i] = (e < 4) ? M[k * 4 + e] : B[k * 2 + (e - 4)];
    }
    for (int i = threadIdx.x; i < N_PRE; i += blockDim.x)
        s_pre[i] = g_part[i * N_PART + 0] + g_part[i * N_PART + 1]
                 + g_part[i * N_PART + 2] + g_part[i * N_PART + 3];
    __syncthreads();

    const float2* s_wout2 = reinterpret_cast<const float2*>(s_wout);
    const unsigned w    = threadIdx.x >> 5;        // warp id: phase-1 owner AND level 13..15 bits
    const unsigned lane = threadIdx.x & 31u;
    const unsigned Pb   = blockIdx.x * PPB;

    // ---- phase 1 (parallel): warp w computes checkpoint for prefix Pb + w ----
    {
        const unsigned P = Pb + w;
        int c = lane;                               // lane = channel
        float A = s_pre[4 + c];
        float vax = s_pre[0], vay = s_pre[2];
        float vbx = s_pre[1], vby = s_pre[3];
        #pragma unroll 1
        for (int k = 0; k < BLK_BITS; k++) {
            unsigned b = (P >> k) & 1u;
            float2 wv = s_wout2[k * 32 + c];
            float vsx = b ? vbx : vax;
            float vsy = b ? vby : vay;
            A = fmaf(wv.x, vsx, fmaf(wv.y, vsy, A));
            const float* M = s_tree + k * 12 + b * 6;
            float m00 = M[0], m01 = M[1], m10 = M[2], m11 = M[3], c0 = M[4], c1 = M[5];
            float nax = fmaf(m00, vax, fmaf(m01, vay, c0));
            float nay = fmaf(m10, vax, fmaf(m11, vay, c1));
            float nbx = fmaf(m00, vbx, fmaf(m01, vby, c0));
            float nby = fmaf(m10, vbx, fmaf(m11, vby, c1));
            vax = nax; vay = nay; vbx = nbx; vby = nby;
        }
        s_A13[w][c] = A;
        if (lane == 0) {
            float4 v4; v4.x = vax; v4.y = vay; v4.z = vbx; v4.w = vby;
            *reinterpret_cast<float4*>(&s_v13[w][0]) = v4;
        }
    }

    const unsigned c4 = lane & 7u;                 // channel group (4 channels)
    const unsigned rr = lane >> 3;                 // 2 bits: levels 16..17

    // ---- per-thread affine composition of levels 13..17 (it-invariant) ----
    float R00 = 1.f, R01 = 0.f, R10 = 0.f, R11 = 1.f, rc0 = 0.f, rc1 = 0.f;
    float pa0 = 0.f, pa1 = 0.f, pa2 = 0.f, pa3 = 0.f;
    float qa0 = 0.f, qa1 = 0.f, qa2 = 0.f, qa3 = 0.f;
    float pb0 = 0.f, pb1 = 0.f, pb2 = 0.f, pb3 = 0.f;
    float qb0 = 0.f, qb1 = 0.f, qb2 = 0.f, qb3 = 0.f;
    float kk0 = 0.f, kk1 = 0.f, kk2 = 0.f, kk3 = 0.f;
    #pragma unroll
    for (int j = 0; j < 5; j++) {
        const int k = BLK_BITS + j;                 // 13..17
        unsigned b = (j < 3) ? ((w >> j) & 1u) : ((rr >> (j - 3)) & 1u);
        float sA = b ? 0.f : 1.f;
        float sB = b ? 1.f : 0.f;
        const float2* W = s_wout2 + k * 32 + c4 * 4;
        #pragma unroll
        for (int i = 0; i < 4; i++) {
            float2 w2 = W[i];
            float wRx = fmaf(w2.x, R00, w2.y * R10);
            float wRy = fmaf(w2.x, R01, w2.y * R11);
            float kc  = fmaf(w2.x, rc0, w2.y * rc1);
            float* PA = (i == 0) ? &pa0 : (i == 1) ? &pa1 : (i == 2) ? &pa2 : &pa3;
            float* QA = (i == 0) ? &qa0 : (i == 1) ? &qa1 : (i == 2) ? &qa2 : &qa3;
            float* PB = (i == 0) ? &pb0 : (i == 1) ? &pb1 : (i == 2) ? &pb2 : &pb3;
            float* QB = (i == 0) ? &qb0 : (i == 1) ? &qb1 : (i == 2) ? &qb2 : &qb3;
            float* KK = (i == 0) ? &kk0 : (i == 1) ? &kk1 : (i == 2) ? &kk2 : &kk3;
            *PA = fmaf(sA, wRx, *PA);
            *QA = fmaf(sA, wRy, *QA);
            *PB = fmaf(sB, wRx, *PB);
            *QB = fmaf(sB, wRy, *QB);
            *KK += kc;
        }
        const float* M = s_tree + k * 12 + b * 6;
        float m00 = M[0], m01 = M[1], m10 = M[2], m11 = M[3], c0 = M[4], c1 = M[5];
        float n00 = fmaf(m00, R00, m01 * R10), n01 = fmaf(m00, R01, m01 * R11);
        float n10 = fmaf(m10, R00, m11 * R10), n11 = fmaf(m10, R01, m11 * R11);
        float nr0 = fmaf(m00, rc0, fmaf(m01, rc1, c0));
        float nr1 = fmaf(m10, rc0, fmaf(m11, rc1, c1));
        R00 = n00; R01 = n01; R10 = n10; R11 = n11; rc0 = nr0; rc1 = nr1;
    }

    // ---- hoist ALL suffix constants (levels 18..20) into registers ----
    const float2* W18 = s_wout2 + 18 * 32 + c4 * 4;
    const float2* W19 = s_wout2 + 19 * 32 + c4 * 4;
    const float2* W20 = s_wout2 + 20 * 32 + c4 * 4;
    float2 u18a = W18[0], u18b = W18[1], u18c = W18[2], u18d = W18[3];
    float2 u19a = W19[0], u19b = W19[1], u19c = W19[2], u19d = W19[3];
    float2 u20a = W20[0], u20b = W20[1], u20c = W20[2], u20d = W20[3];
    float M18[12], M19[12];
    #pragma unroll
    for (int i = 0; i < 12; i++) M18[i] = s_tree[18 * 12 + i];
    #pragma unroll
    for (int i = 0; i < 12; i++) M19[i] = s_tree[19 * 12 + i];

    __syncthreads();

    // ---- phase 2: expand each of the 8 checkpoints ----
    #pragma unroll 1
    for (int it = 0; it < PPB; ++it) {
        const float4 af = *reinterpret_cast<const float4*>(&s_A13[it][c4 * 4]);
        const float4 vf = *reinterpret_cast<const float4*>(&s_v13[it][0]);
        const float v13ax = vf.x, v13ay = vf.y, v13bx = vf.z, v13by = vf.w;

        // jump to level 18 via the composed affine map
        float A0 = fmaf(pa0, v13ax, fmaf(qa0, v13ay, fmaf(pb0, v13bx, fmaf(qb0, v13by, af.x + kk0))));
        float A1 = fmaf(pa1, v13ax, fmaf(qa1, v13ay, fmaf(pb1, v13bx, fmaf(qb1, v13by, af.y + kk1))));
        float A2 = fmaf(pa2, v13ax, fmaf(qa2, v13ay, fmaf(pb2, v13bx, fmaf(qb2, v13by, af.z + kk2))));
        float A3 = fmaf(pa3, v13ax, fmaf(qa3, v13ay, fmaf(pb3, v13bx, fmaf(qb3, v13by, af.w + kk3))));
        float vax = fmaf(R00, v13ax, fmaf(R01, v13ay, rc0));
        float vay = fmaf(R10, v13ax, fmaf(R11, v13ay, rc1));
        float vbx = fmaf(R00, v13bx, fmaf(R01, v13by, rc0));
        float vby = fmaf(R10, v13bx, fmaf(R11, v13by, rc1));

        const unsigned p_base = (Pb + it) | (w << 13) | (rr << 16);

        // suffix enumeration: b1 = s19 (level 18), b2 = s20 (level 19)
        #pragma unroll
        for (unsigned u = 0; u < 4; ++u) {
            const unsigned b1 = u & 1u, b2 = (u >> 1) & 1u;

            float vs18x = b1 ? vbx : vax;
            float vs18y = b1 ? vby : vay;
            float m00 = M18[b1 * 6 + 0], m01 = M18[b1 * 6 + 1];
            float m10 = M18[b1 * 6 + 2], m11 = M18[b1 * 6 + 3];
            float c0  = M18[b1 * 6 + 4], c1  = M18[b1 * 6 + 5];
            float pax = fmaf(m00, vax, fmaf(m01, vay, c0));
            float pay = fmaf(m10, vax, fmaf(m11, vay, c1));
            float pbx = fmaf(m00, vbx, fmaf(m01, vby, c0));
            float pby = fmaf(m10, vbx, fmaf(m11, vby, c1));

            float vs19x = b2 ? pbx : pax;
            float vs19y = b2 ? pby : pay;
            m00 = M19[b2 * 6 + 0]; m01 = M19[b2 * 6 + 1];
            m10 = M19[b2 * 6 + 2]; m11 = M19[b2 * 6 + 3];
            c0  = M19[b2 * 6 + 4]; c1  = M19[b2 * 6 + 5];
            float qax = fmaf(m00, pax, fmaf(m01, pay, c0));
            float qay = fmaf(m10, pax, fmaf(m11, pay, c1));
            float qbx = fmaf(m00, pbx, fmaf(m01, pby, c0));
            float qby = fmaf(m10, pbx, fmaf(m11, pby, c1));

            float P0 = fmaf(u19a.x, vs19x, fmaf(u19a.y, vs19y,
                       fmaf(u18a.x, vs18x, fmaf(u18a.y, vs18y, A0))));
            float P1 = fmaf(u19b.x, vs19x, fmaf(u19b.y, vs19y,
                       fmaf(u18b.x, vs18x, fmaf(u18b.y, vs18y, A1))));
            float P2 = fmaf(u19c.x, vs19x, fmaf(u19c.y, vs19y,
                       fmaf(u18c.x, vs18x, fmaf(u18c.y, vs18y, A2))));
            float P3 = fmaf(u19d.x, vs19x, fmaf(u19d.y, vs19y,
                       fmaf(u18d.x, vs18x, fmaf(u18d.y, vs18y, A3))));

            unsigned p = p_base | (b1 << 18) | (b2 << 19);
            float* o = out + (size_t)p * OUT_DIM + c4 * 4;

            float4 r0, r1;
            r0.x = fmaf(u20a.x, qax, fmaf(u20a.y, qay, P0));
            r0.y = fmaf(u20b.x, qax, fmaf(u20b.y, qay, P1));
            r0.z = fmaf(u20c.x, qax, fmaf(u20c.y, qay, P2));
            r0.w = fmaf(u20d.x, qax, fmaf(u20d.y, qay, P3));
            r1.x = fmaf(u20a.x, qbx, fmaf(u20a.y, qby, P0));
            r1.y = fmaf(u20b.x, qbx, fmaf(u20b.y, qby, P1));
            r1.z = fmaf(u20c.x, qbx, fmaf(u20c.y, qby, P2));
            r1.w = fmaf(u20d.x, qbx, fmaf(u20d.y, qby, P3));

            __stcs(reinterpret_cast<float4*>(o), r0);
            __stcs(reinterpret_cast<float4*>(o + ((size_t)1u << 20) * OUT_DIM), r1);
        }
    }
}

// ---------------------------------------------------------------------------
extern "C" void kernel_launch(void* const* d_in, const int* in_sizes, int n_in,
                              void* d_out, int out_size)
{
    const float* x    = (const float*)d_in[0];
    const float* wl   = (const float*)d_in[1];
    const float* wr   = (const float*)d_in[2];
    const float* bl   = (const float*)d_in[3];
    const float* br   = (const float*)d_in[4];
    const float* tl   = (const float*)d_in[5];
    const float* tr   = (const float*)d_in[6];
    const float* tbl  = (const float*)d_in[7];
    const float* tbr  = (const float*)d_in[8];
    const float* w0   = (const float*)d_in[9];
    const float* wout = (const float*)d_in[10];
    const float* ob   = (const float*)d_in[11];

    precompute_kernel<<<N_PRE * N_PART, 256>>>(x, wl, wr, bl, br, w0, ob);

    tree_kernel<<<(1 << BLK_BITS) / PPB, 256>>>(tl, tr, tbl, tbr, wout, (float*)d_out);
}